// round 2
// baseline (speedup 1.0000x reference)
#include <cuda_runtime.h>
#include <cstdint>

#define B_ 4
#define H_ 16
#define S_ 2048
#define D_ 64
#define BR 64          // query rows per CTA
#define BC 64          // key cols per tile
#define SK 68          // K smem stride (mod 32 == 4 -> conflict-free K frag reads)
#define SV 72          // V smem stride (mod 32 == 8 -> conflict-free V frag reads)

#define SMEM_FLOATS (2*BR*SK + 2*BR*SV)
#define SMEM_BYTES  (SMEM_FLOATS * 4)

__device__ __forceinline__ uint32_t f2tf(float x) {
    uint32_t r;
    asm("cvt.rna.tf32.f32 %0, %1;" : "=r"(r) : "f"(x));
    return r;
}
__device__ __forceinline__ float ex2f(float x) {
    float y;
    asm("ex2.approx.f32 %0, %1;" : "=f"(y) : "f"(x));
    return y;
}
__device__ __forceinline__ uint32_t s2u(const void* p) {
    uint32_t a;
    asm("{.reg .u64 t; cvta.to.shared.u64 t, %1; cvt.u32.u64 %0, t;}" : "=r"(a) : "l"(p));
    return a;
}
__device__ __forceinline__ void cpa16(uint32_t dst, const void* src) {
    asm volatile("cp.async.cg.shared.global [%0], [%1], 16;" :: "r"(dst), "l"(src));
}
__device__ __forceinline__ void mma_tf32(float* c, const uint32_t* a, uint32_t b0, uint32_t b1) {
    asm volatile(
        "mma.sync.aligned.m16n8k8.row.col.f32.tf32.tf32.f32 "
        "{%0,%1,%2,%3},{%4,%5,%6,%7},{%8,%9},{%0,%1,%2,%3};"
        : "+f"(c[0]), "+f"(c[1]), "+f"(c[2]), "+f"(c[3])
        : "r"(a[0]), "r"(a[1]), "r"(a[2]), "r"(a[3]), "r"(b0), "r"(b1));
}

__global__ __launch_bounds__(128, 2)
void fa_tf32_v2(const float* __restrict__ Q,
                const float* __restrict__ K,
                const float* __restrict__ V,
                const int* __restrict__ to_mask,
                float* __restrict__ O) {
    extern __shared__ float smem[];
    float* sKbuf[2] = { smem,              smem + BR*SK };
    float* sVbuf[2] = { smem + 2*BR*SK,    smem + 2*BR*SK + BR*SV };

    const int qt   = (int)gridDim.x - 1 - (int)blockIdx.x;   // heavy tiles first
    const int bh   = blockIdx.y;
    const int tid  = threadIdx.x;
    const int w    = tid >> 5;
    const int lane = tid & 31;
    const int g    = lane >> 2;
    const int t    = lane & 3;
    const int msk  = to_mask[0];

    // copy-lane mapping: 8x float4 per thread per tile
    const int r0c = tid >> 4;            // base row (0..7), rows r0c + 8i
    const int cc  = (tid & 15) * 4;      // float col

    const float* Qb = Q + ((size_t)bh * S_ + (size_t)qt * BR) * D_;
    const float* Kb = K + (size_t)bh * S_ * D_;
    const float* Vb = V + (size_t)bh * S_ * D_;

    uint32_t kAddr[2] = { s2u(sKbuf[0]), s2u(sKbuf[1]) };
    uint32_t vAddr[2] = { s2u(sVbuf[0]), s2u(sVbuf[1]) };

    const int ntiles = msk ? (qt + 1) : (S_ / BC);

    // ---- prologue: async-load tile 0 (K,V) ----
    #pragma unroll
    for (int i = 0; i < 8; i++) {
        int r = r0c + 8 * i;
        cpa16(kAddr[0] + (uint32_t)(r * SK + cc) * 4, Kb + (size_t)r * D_ + cc);
        cpa16(vAddr[0] + (uint32_t)(r * SV + cc) * 4, Vb + (size_t)r * D_ + cc);
    }
    asm volatile("cp.async.commit_group;" ::: "memory");

    // ---- Q staging in sKbuf[1] (consumed before tile 1 overwrites it) ----
    #pragma unroll
    for (int i = 0; i < 8; i++) {
        int r = r0c + 8 * i;
        float4 q = *reinterpret_cast<const float4*>(Qb + (size_t)r * D_ + cc);
        *reinterpret_cast<float4*>(&sKbuf[1][r * SK + cc]) = q;
    }
    __syncthreads();

    // scale = 1/sqrt(64) * log2(e): softmax done in base-2
    const float QSC = 0.125f * 1.44269504088896f;
    uint32_t qa[8][4];
    {
        const int r0 = w * 16 + g;
        const float* bq = sKbuf[1];
        #pragma unroll
        for (int kk = 0; kk < 8; kk++) {
            qa[kk][0] = f2tf(QSC * bq[r0 * SK + kk * 8 + t]);
            qa[kk][1] = f2tf(QSC * bq[(r0 + 8) * SK + kk * 8 + t]);
            qa[kk][2] = f2tf(QSC * bq[r0 * SK + kk * 8 + t + 4]);
            qa[kk][3] = f2tf(QSC * bq[(r0 + 8) * SK + kk * 8 + t + 4]);
        }
    }

    float o[8][4];
    #pragma unroll
    for (int nt = 0; nt < 8; nt++) { o[nt][0]=0.f; o[nt][1]=0.f; o[nt][2]=0.f; o[nt][3]=0.f; }
    float m0 = -1e30f, m1 = -1e30f, l0 = 0.f, l1 = 0.f;

    const int src1 = (lane & ~3) | (t >> 1);
    const int src2 = src1 + 2;
    const bool par = (t & 1);

    for (int j = 0; j < ntiles; j++) {
        __syncthreads();   // all warps finished reading the buffer we overwrite next
        if (j + 1 < ntiles) {
            const int buf = (j + 1) & 1;
            const float* Kt = Kb + (size_t)(j + 1) * BC * D_;
            const float* Vt = Vb + (size_t)(j + 1) * BC * D_;
            #pragma unroll
            for (int i = 0; i < 8; i++) {
                int r = r0c + 8 * i;
                cpa16(kAddr[buf] + (uint32_t)(r * SK + cc) * 4, Kt + (size_t)r * D_ + cc);
                cpa16(vAddr[buf] + (uint32_t)(r * SV + cc) * 4, Vt + (size_t)r * D_ + cc);
            }
            asm volatile("cp.async.commit_group;" ::: "memory");
            asm volatile("cp.async.wait_group 1;" ::: "memory");
        } else {
            asm volatile("cp.async.wait_group 0;" ::: "memory");
        }
        __syncthreads();

        const float* kj = sKbuf[j & 1];
        const float* vj = sVbuf[j & 1];

        // ---- S = (Q * qsc) K^T : kk outer -> 8 independent accum chains ----
        float s[8][4];
        #pragma unroll
        for (int nt = 0; nt < 8; nt++) { s[nt][0]=0.f; s[nt][1]=0.f; s[nt][2]=0.f; s[nt][3]=0.f; }
        #pragma unroll
        for (int kk = 0; kk < 8; kk++) {
            #pragma unroll
            for (int nt = 0; nt < 8; nt++) {
                uint32_t b0 = f2tf(kj[(nt * 8 + g) * SK + kk * 8 + t]);
                uint32_t b1 = f2tf(kj[(nt * 8 + g) * SK + kk * 8 + t + 4]);
                mma_tf32(s[nt], qa[kk], b0, b1);
            }
        }

        // ---- causal mask on the diagonal tile ----
        if (msk && j == qt) {
            const int row0 = qt * BR + w * 16 + g;
            #pragma unroll
            for (int nt = 0; nt < 8; nt++) {
                int col = j * BC + nt * 8 + 2 * t;
                if (col     > row0)     s[nt][0] = -1e30f;
                if (col + 1 > row0)     s[nt][1] = -1e30f;
                if (col     > row0 + 8) s[nt][2] = -1e30f;
                if (col + 1 > row0 + 8) s[nt][3] = -1e30f;
            }
        }

        // ---- online softmax (base-2) ----
        float tm0 = -1e30f, tm1 = -1e30f;
        #pragma unroll
        for (int nt = 0; nt < 8; nt++) {
            tm0 = fmaxf(tm0, fmaxf(s[nt][0], s[nt][1]));
            tm1 = fmaxf(tm1, fmaxf(s[nt][2], s[nt][3]));
        }
        #pragma unroll
        for (int off = 1; off < 4; off <<= 1) {
            tm0 = fmaxf(tm0, __shfl_xor_sync(0xffffffffu, tm0, off));
            tm1 = fmaxf(tm1, __shfl_xor_sync(0xffffffffu, tm1, off));
        }
        const float mn0 = fmaxf(m0, tm0), mn1 = fmaxf(m1, tm1);
        const float c0 = ex2f(m0 - mn0), c1 = ex2f(m1 - mn1);
        float ps0 = 0.f, ps1 = 0.f;
        #pragma unroll
        for (int nt = 0; nt < 8; nt++) {
            s[nt][0] = ex2f(s[nt][0] - mn0);
            s[nt][1] = ex2f(s[nt][1] - mn0);
            s[nt][2] = ex2f(s[nt][2] - mn1);
            s[nt][3] = ex2f(s[nt][3] - mn1);
            ps0 += s[nt][0] + s[nt][1];
            ps1 += s[nt][2] + s[nt][3];
        }
        l0 = l0 * c0 + ps0;  l1 = l1 * c1 + ps1;
        m0 = mn0;            m1 = mn1;
        #pragma unroll
        for (int nt = 0; nt < 8; nt++) {
            o[nt][0] *= c0; o[nt][1] *= c0; o[nt][2] *= c1; o[nt][3] *= c1;
        }

        // ---- O += P V : P A-fragments built in registers via shuffles ----
        #pragma unroll
        for (int kk = 0; kk < 8; kk++) {
            float x00 = __shfl_sync(0xffffffffu, s[kk][0], src1);
            float x01 = __shfl_sync(0xffffffffu, s[kk][1], src1);
            float x10 = __shfl_sync(0xffffffffu, s[kk][2], src1);
            float x11 = __shfl_sync(0xffffffffu, s[kk][3], src1);
            float y00 = __shfl_sync(0xffffffffu, s[kk][0], src2);
            float y01 = __shfl_sync(0xffffffffu, s[kk][1], src2);
            float y10 = __shfl_sync(0xffffffffu, s[kk][2], src2);
            float y11 = __shfl_sync(0xffffffffu, s[kk][3], src2);
            uint32_t a[4];
            a[0] = f2tf(par ? x01 : x00);
            a[1] = f2tf(par ? x11 : x10);
            a[2] = f2tf(par ? y01 : y00);
            a[3] = f2tf(par ? y11 : y10);
            #pragma unroll
            for (int nt = 0; nt < 8; nt++) {
                uint32_t b0 = f2tf(vj[(kk * 8 + t) * SV + nt * 8 + g]);
                uint32_t b1 = f2tf(vj[(kk * 8 + t + 4) * SV + nt * 8 + g]);
                mma_tf32(o[nt], a, b0, b1);
            }
        }
    }

    // ---- epilogue ----
    #pragma unroll
    for (int off = 1; off < 4; off <<= 1) {
        l0 += __shfl_xor_sync(0xffffffffu, l0, off);
        l1 += __shfl_xor_sync(0xffffffffu, l1, off);
    }
    const float inv0 = 1.f / l0, inv1 = 1.f / l1;
    const int row0 = qt * BR + w * 16 + g;
    float* Ob = O + (size_t)bh * S_ * D_;
    #pragma unroll
    for (int nt = 0; nt < 8; nt++) {
        int col = nt * 8 + 2 * t;
        *reinterpret_cast<float2*>(Ob + (size_t)row0 * D_ + col) =
            make_float2(o[nt][0] * inv0, o[nt][1] * inv0);
        *reinterpret_cast<float2*>(Ob + (size_t)(row0 + 8) * D_ + col) =
            make_float2(o[nt][2] * inv1, o[nt][3] * inv1);
    }
}

extern "C" void kernel_launch(void* const* d_in, const int* in_sizes, int n_in,
                              void* d_out, int out_size) {
    const float* Q = (const float*)d_in[0];
    const float* K = (const float*)d_in[1];
    const float* V = (const float*)d_in[2];
    const int* msk = (const int*)d_in[3];
    float* O = (float*)d_out;

    cudaFuncSetAttribute(fa_tf32_v2, cudaFuncAttributeMaxDynamicSharedMemorySize, SMEM_BYTES);
    dim3 grid(S_ / BR, B_ * H_);
    fa_tf32_v2<<<grid, 128, SMEM_BYTES>>>(Q, K, V, msk, O);
}

// round 4
// speedup vs baseline: 1.9563x; 1.9563x over previous
#include <cuda_runtime.h>
#include <cstdint>

#define B_ 4
#define H_ 16
#define S_ 2048
#define D_ 64
#define BR 64            // query rows per CTA (4 warps x 16)
#define BC 64            // key cols per tile

// dynamic smem layout (bytes)
#define SM_F32K 0
#define SM_F32V 16384
#define SM_K16  32768                 // 64 rows x 144B
#define SM_V16  (32768 + 9216)
#define SM_BYTES (32768 + 9216 + 9216)

#define RSTRIDE 144                   // fp16 row stride in bytes (64 halves + 8 pad)

static __device__ __forceinline__ float ex2f(float x) {
    float y; asm("ex2.approx.f32 %0, %1;" : "=f"(y) : "f"(x)); return y;
}
// pack {lo, hi} floats -> f16x2 (lo in low 16 bits)
static __device__ __forceinline__ uint32_t pk(float lo, float hi) {
    uint32_t d; asm("cvt.rn.f16x2.f32 %0, %1, %2;" : "=r"(d) : "f"(hi), "f"(lo)); return d;
}
static __device__ __forceinline__ uint32_t s2u(const void* p) {
    uint32_t a;
    asm("{.reg .u64 t; cvta.to.shared.u64 t, %1; cvt.u32.u64 %0, t;}" : "=r"(a) : "l"(p));
    return a;
}
static __device__ __forceinline__ void cpa16(uint32_t dst, const void* src) {
    asm volatile("cp.async.cg.shared.global [%0], [%1], 16;" :: "r"(dst), "l"(src));
}
static __device__ __forceinline__ void ldm4(uint32_t* r, uint32_t a) {
    asm volatile("ldmatrix.sync.aligned.m8n8.x4.shared.b16 {%0,%1,%2,%3}, [%4];"
                 : "=r"(r[0]), "=r"(r[1]), "=r"(r[2]), "=r"(r[3]) : "r"(a));
}
static __device__ __forceinline__ void ldm4t(uint32_t* r, uint32_t a) {
    asm volatile("ldmatrix.sync.aligned.m8n8.x4.trans.shared.b16 {%0,%1,%2,%3}, [%4];"
                 : "=r"(r[0]), "=r"(r[1]), "=r"(r[2]), "=r"(r[3]) : "r"(a));
}
static __device__ __forceinline__ void mma16816(float* c, const uint32_t* a,
                                                uint32_t b0, uint32_t b1) {
    asm volatile(
        "mma.sync.aligned.m16n8k16.row.col.f32.f16.f16.f32 "
        "{%0,%1,%2,%3},{%4,%5,%6,%7},{%8,%9},{%0,%1,%2,%3};"
        : "+f"(c[0]), "+f"(c[1]), "+f"(c[2]), "+f"(c[3])
        : "r"(a[0]), "r"(a[1]), "r"(a[2]), "r"(a[3]), "r"(b0), "r"(b1));
}

__global__ __launch_bounds__(128, 3)
void fa_fp16(const float* __restrict__ Q,
             const float* __restrict__ K,
             const float* __restrict__ V,
             const int* __restrict__ to_mask,
             float* __restrict__ O) {
    extern __shared__ char smem[];
    const uint32_t sb = s2u(smem);

    const int tid  = threadIdx.x;
    const int w    = tid >> 5;
    const int lane = tid & 31;
    const int g    = lane >> 2;
    const int t    = lane & 3;
    const int qt   = (int)gridDim.x - 1 - (int)blockIdx.x;   // heavy tiles first
    const int bh   = blockIdx.y;
    const int msk  = to_mask[0];

    const float* Qb = Q + ((size_t)bh * S_ + (size_t)qt * BR) * D_;   // 4096 contiguous f32
    const float* Kb = K + (size_t)bh * S_ * D_;
    const float* Vb = V + (size_t)bh * S_ * D_;

    const int ntiles = msk ? (qt + 1) : (S_ / BC);

    // ---- prologue: cp.async tile 0 (f32 K,V, flat 4096 each) ----
    #pragma unroll
    for (int i = 0; i < 8; i++) {
        int f = tid + i * 128;                 // float4 index
        cpa16(sb + SM_F32K + f * 16, Kb + f * 4);
        cpa16(sb + SM_F32V + f * 16, Vb + f * 4);
    }
    asm volatile("cp.async.commit_group;" ::: "memory");

    // ---- stage Q: f32 gmem -> scaled fp16 in K16 buffer, then ldmatrix frags ----
    const float QSC = 0.125f * 1.44269504088896341f;      // 1/sqrt(64) * log2(e)
    {
        const float4* Q4 = reinterpret_cast<const float4*>(Qb);
        char* k16 = smem + SM_K16;
        #pragma unroll
        for (int i = 0; i < 4; i++) {
            int ci = tid + i * 128;                        // 16B-chunk index (8 halves)
            float4 x = Q4[2 * ci];
            float4 y = Q4[2 * ci + 1];
            uint4 h;
            h.x = pk(x.x * QSC, x.y * QSC);
            h.y = pk(x.z * QSC, x.w * QSC);
            h.z = pk(y.x * QSC, y.y * QSC);
            h.w = pk(y.z * QSC, y.w * QSC);
            *reinterpret_cast<uint4*>(k16 + (ci >> 3) * RSTRIDE + (ci & 7) * 16) = h;
        }
    }
    __syncthreads();

    uint32_t qa[4][4];                                    // A frags: 4 ksteps
    {
        const uint32_t qbase = sb + SM_K16 + (w * 16 + (lane & 15)) * RSTRIDE + (lane >> 4) * 16;
        #pragma unroll
        for (int ks = 0; ks < 4; ks++) ldm4(qa[ks], qbase + ks * 32);
    }

    float o[8][4];
    #pragma unroll
    for (int nt = 0; nt < 8; nt++) { o[nt][0]=0.f; o[nt][1]=0.f; o[nt][2]=0.f; o[nt][3]=0.f; }
    float m0 = -1e30f, m1 = -1e30f, l0 = 0.f, l1 = 0.f;

    // per-thread ldmatrix base addrs
    const uint32_t kfb = sb + SM_K16 + (lane & 7) * RSTRIDE + (lane >> 3) * 16;
    const uint32_t vfb = sb + SM_V16 + lane * RSTRIDE;

    for (int j = 0; j < ntiles; j++) {
        asm volatile("cp.async.wait_group 0;" ::: "memory");
        __syncthreads();                                   // tile j f32 visible; prev compute done

        // ---- convert f32 -> fp16 (K natural, V natural; both 144B-stride rows) ----
        {
            const float4* K4 = reinterpret_cast<const float4*>(smem + SM_F32K);
            const float4* V4 = reinterpret_cast<const float4*>(smem + SM_F32V);
            char* k16 = smem + SM_K16;
            char* v16 = smem + SM_V16;
            #pragma unroll
            for (int i = 0; i < 4; i++) {
                int ci = tid + i * 128;
                int dst = (ci >> 3) * RSTRIDE + (ci & 7) * 16;
                float4 x = K4[2 * ci], y = K4[2 * ci + 1];
                uint4 h;
                h.x = pk(x.x, x.y); h.y = pk(x.z, x.w);
                h.z = pk(y.x, y.y); h.w = pk(y.z, y.w);
                *reinterpret_cast<uint4*>(k16 + dst) = h;
                x = V4[2 * ci]; y = V4[2 * ci + 1];
                h.x = pk(x.x, x.y); h.y = pk(x.z, x.w);
                h.z = pk(y.x, y.y); h.w = pk(y.z, y.w);
                *reinterpret_cast<uint4*>(v16 + dst) = h;
            }
        }
        __syncthreads();

        // ---- prefetch tile j+1 (overlaps with compute below) ----
        if (j + 1 < ntiles) {
            const float* Kt = Kb + (size_t)(j + 1) * BC * D_;
            const float* Vt = Vb + (size_t)(j + 1) * BC * D_;
            #pragma unroll
            for (int i = 0; i < 8; i++) {
                int f = tid + i * 128;
                cpa16(sb + SM_F32K + f * 16, Kt + f * 4);
                cpa16(sb + SM_F32V + f * 16, Vt + f * 4);
            }
            asm volatile("cp.async.commit_group;" ::: "memory");
        }

        // ---- S = Q K^T  (32 MMA + 16 ldmatrix per warp) ----
        float s[8][4];
        #pragma unroll
        for (int nt = 0; nt < 8; nt++) { s[nt][0]=0.f; s[nt][1]=0.f; s[nt][2]=0.f; s[nt][3]=0.f; }
        #pragma unroll
        for (int nt = 0; nt < 8; nt++) {
            uint32_t b[8];
            ldm4(b,     kfb + nt * (8 * RSTRIDE));          // k chunks 0..3
            ldm4(b + 4, kfb + nt * (8 * RSTRIDE) + 64);     // k chunks 4..7
            mma16816(s[nt], qa[0], b[0], b[1]);
            mma16816(s[nt], qa[1], b[2], b[3]);
            mma16816(s[nt], qa[2], b[4], b[5]);
            mma16816(s[nt], qa[3], b[6], b[7]);
        }

        // ---- causal mask on diagonal tile ----
        if (msk && j == qt) {
            const int row0 = qt * BR + w * 16 + g;
            #pragma unroll
            for (int nt = 0; nt < 8; nt++) {
                int col = j * BC + nt * 8 + 2 * t;
                if (col     > row0)     s[nt][0] = -1e30f;
                if (col + 1 > row0)     s[nt][1] = -1e30f;
                if (col     > row0 + 8) s[nt][2] = -1e30f;
                if (col + 1 > row0 + 8) s[nt][3] = -1e30f;
            }
        }

        // ---- online softmax (base-2) ----
        float tm0 = -1e30f, tm1 = -1e30f;
        #pragma unroll
        for (int nt = 0; nt < 8; nt++) {
            tm0 = fmaxf(tm0, fmaxf(s[nt][0], s[nt][1]));
            tm1 = fmaxf(tm1, fmaxf(s[nt][2], s[nt][3]));
        }
        #pragma unroll
        for (int off = 1; off < 4; off <<= 1) {
            tm0 = fmaxf(tm0, __shfl_xor_sync(0xffffffffu, tm0, off));
            tm1 = fmaxf(tm1, __shfl_xor_sync(0xffffffffu, tm1, off));
        }
        const float mn0 = fmaxf(m0, tm0), mn1 = fmaxf(m1, tm1);
        const float c0 = ex2f(m0 - mn0), c1 = ex2f(m1 - mn1);
        float ps0 = 0.f, ps1 = 0.f;
        #pragma unroll
        for (int nt = 0; nt < 8; nt++) {
            s[nt][0] = ex2f(s[nt][0] - mn0);
            s[nt][1] = ex2f(s[nt][1] - mn0);
            s[nt][2] = ex2f(s[nt][2] - mn1);
            s[nt][3] = ex2f(s[nt][3] - mn1);
            ps0 += s[nt][0] + s[nt][1];
            ps1 += s[nt][2] + s[nt][3];
        }
        l0 = l0 * c0 + ps0;  l1 = l1 * c1 + ps1;
        m0 = mn0;            m1 = mn1;
        #pragma unroll
        for (int nt = 0; nt < 8; nt++) {
            o[nt][0] *= c0; o[nt][1] *= c0; o[nt][2] *= c1; o[nt][3] *= c1;
        }

        // ---- P C-frags -> A-frags (pure register packs) ----
        uint32_t pa[4][4];
        #pragma unroll
        for (int ks = 0; ks < 4; ks++) {
            pa[ks][0] = pk(s[2*ks][0],   s[2*ks][1]);     // row g,   k=2t,2t+1
            pa[ks][1] = pk(s[2*ks][2],   s[2*ks][3]);     // row g+8
            pa[ks][2] = pk(s[2*ks+1][0], s[2*ks+1][1]);   // row g,   k=2t+8,2t+9
            pa[ks][3] = pk(s[2*ks+1][2], s[2*ks+1][3]);   // row g+8
        }

        // ---- O += P V  (32 MMA + 16 ldmatrix.trans per warp) ----
        #pragma unroll
        for (int nt = 0; nt < 8; nt++) {
            uint32_t b[8];
            ldm4t(b,     vfb + nt * 16);                   // s rows 0..31
            ldm4t(b + 4, vfb + nt * 16 + 32 * RSTRIDE);    // s rows 32..63
            mma16816(o[nt], pa[0], b[0], b[1]);
            mma16816(o[nt], pa[1], b[2], b[3]);
            mma16816(o[nt], pa[2], b[4], b[5]);
            mma16816(o[nt], pa[3], b[6], b[7]);
        }
    }

    // ---- epilogue ----
    #pragma unroll
    for (int off = 1; off < 4; off <<= 1) {
        l0 += __shfl_xor_sync(0xffffffffu, l0, off);
        l1 += __shfl_xor_sync(0xffffffffu, l1, off);
    }
    const float inv0 = 1.f / l0, inv1 = 1.f / l1;
    const int row0 = qt * BR + w * 16 + g;
    float* Ob = O + (size_t)bh * S_ * D_;
    #pragma unroll
    for (int nt = 0; nt < 8; nt++) {
        int col = nt * 8 + 2 * t;
        *reinterpret_cast<float2*>(Ob + (size_t)row0 * D_ + col) =
            make_float2(o[nt][0] * inv0, o[nt][1] * inv0);
        *reinterpret_cast<float2*>(Ob + (size_t)(row0 + 8) * D_ + col) =
            make_float2(o[nt][2] * inv1, o[nt][3] * inv1);
    }
}

extern "C" void kernel_launch(void* const* d_in, const int* in_sizes, int n_in,
                              void* d_out, int out_size) {
    const float* Q = (const float*)d_in[0];
    const float* K = (const float*)d_in[1];
    const float* V = (const float*)d_in[2];
    const int* msk = (const int*)d_in[3];
    float* O = (float*)d_out;

    cudaFuncSetAttribute(fa_fp16, cudaFuncAttributeMaxDynamicSharedMemorySize, SM_BYTES);
    dim3 grid(S_ / BR, B_ * H_);
    fa_fp16<<<grid, 128, SM_BYTES>>>(Q, K, V, msk, O);
}

// round 5
// speedup vs baseline: 2.3009x; 1.1762x over previous
#include <cuda_runtime.h>
#include <cstdint>

#define B_ 4
#define H_ 16
#define S_ 2048
#define D_ 64
#define BR 128           // query rows per CTA (4 warps x 32)
#define BC 64            // key cols per tile

// dynamic smem layout (bytes)
#define SM_F32K 0
#define SM_F32V 16384
#define SM_K16  32768                 // 64 rows x 144B (also Q staging rows 0..63)
#define SM_V16  (32768 + 9216)        // 64 rows x 144B (also Q staging rows 64..127)
#define SM_BYTES (32768 + 9216 + 9216)

#define RSTRIDE 144                   // fp16 row stride in bytes (64 halves + 8 pad)

static __device__ __forceinline__ float ex2f(float x) {
    float y; asm("ex2.approx.f32 %0, %1;" : "=f"(y) : "f"(x)); return y;
}
// pack {lo, hi} floats -> f16x2 (lo in low 16 bits)
static __device__ __forceinline__ uint32_t pk(float lo, float hi) {
    uint32_t d; asm("cvt.rn.f16x2.f32 %0, %1, %2;" : "=r"(d) : "f"(hi), "f"(lo)); return d;
}
static __device__ __forceinline__ uint32_t s2u(const void* p) {
    uint32_t a;
    asm("{.reg .u64 t; cvta.to.shared.u64 t, %1; cvt.u32.u64 %0, t;}" : "=r"(a) : "l"(p));
    return a;
}
static __device__ __forceinline__ void cpa16(uint32_t dst, const void* src) {
    asm volatile("cp.async.cg.shared.global [%0], [%1], 16;" :: "r"(dst), "l"(src));
}
static __device__ __forceinline__ void ldm4(uint32_t* r, uint32_t a) {
    asm volatile("ldmatrix.sync.aligned.m8n8.x4.shared.b16 {%0,%1,%2,%3}, [%4];"
                 : "=r"(r[0]), "=r"(r[1]), "=r"(r[2]), "=r"(r[3]) : "r"(a));
}
static __device__ __forceinline__ void ldm4t(uint32_t* r, uint32_t a) {
    asm volatile("ldmatrix.sync.aligned.m8n8.x4.trans.shared.b16 {%0,%1,%2,%3}, [%4];"
                 : "=r"(r[0]), "=r"(r[1]), "=r"(r[2]), "=r"(r[3]) : "r"(a));
}
static __device__ __forceinline__ void mma16816(float* c, const uint32_t* a,
                                                uint32_t b0, uint32_t b1) {
    asm volatile(
        "mma.sync.aligned.m16n8k16.row.col.f32.f16.f16.f32 "
        "{%0,%1,%2,%3},{%4,%5,%6,%7},{%8,%9},{%0,%1,%2,%3};"
        : "+f"(c[0]), "+f"(c[1]), "+f"(c[2]), "+f"(c[3])
        : "r"(a[0]), "r"(a[1]), "r"(a[2]), "r"(a[3]), "r"(b0), "r"(b1));
}

__global__ __launch_bounds__(128, 2)
void fa_fp16_v2(const float* __restrict__ Q,
                const float* __restrict__ K,
                const float* __restrict__ V,
                const int* __restrict__ to_mask,
                float* __restrict__ O) {
    extern __shared__ char smem[];
    const uint32_t sb = s2u(smem);

    const int tid  = threadIdx.x;
    const int w    = tid >> 5;
    const int lane = tid & 31;
    const int g    = lane >> 2;
    const int t    = lane & 3;
    const int qt   = (int)gridDim.x - 1 - (int)blockIdx.x;   // heavy tiles first
    const int bh   = blockIdx.y;
    const int msk  = to_mask[0];

    const float* Qb = Q + ((size_t)bh * S_ + (size_t)qt * BR) * D_;
    const float* Kb = K + (size_t)bh * S_ * D_;
    const float* Vb = V + (size_t)bh * S_ * D_;

    const int ntiles = msk ? (2 * qt + 2) : (S_ / BC);

    // ---- prologue: cp.async tile 0 (f32 K,V, flat 4096 floats each) ----
    #pragma unroll
    for (int i = 0; i < 8; i++) {
        int f = tid + i * 128;                 // float4 index
        cpa16(sb + SM_F32K + f * 16, Kb + f * 4);
        cpa16(sb + SM_F32V + f * 16, Vb + f * 4);
    }
    asm volatile("cp.async.commit_group;" ::: "memory");

    // ---- stage Q (128x64): f32 gmem -> scaled fp16 spanning K16+V16 region ----
    const float QSC = 0.125f * 1.44269504088896341f;      // 1/sqrt(64) * log2(e)
    {
        const float4* Q4 = reinterpret_cast<const float4*>(Qb);
        char* q16 = smem + SM_K16;
        #pragma unroll
        for (int i = 0; i < 8; i++) {
            int ci = tid + i * 128;                        // 16B-chunk idx (0..1023)
            float4 x = Q4[2 * ci];
            float4 y = Q4[2 * ci + 1];
            uint4 h;
            h.x = pk(x.x * QSC, x.y * QSC);
            h.y = pk(x.z * QSC, x.w * QSC);
            h.z = pk(y.x * QSC, y.y * QSC);
            h.w = pk(y.z * QSC, y.w * QSC);
            *reinterpret_cast<uint4*>(q16 + (ci >> 3) * RSTRIDE + (ci & 7) * 16) = h;
        }
    }
    __syncthreads();

    // two m16 row-tiles per warp: rows w*32 + tb*16 + [0..16)
    uint32_t qa[2][4][4];
    #pragma unroll
    for (int tb = 0; tb < 2; tb++) {
        uint32_t qbase = sb + SM_K16
                       + (w * 32 + tb * 16 + (lane & 15)) * RSTRIDE + (lane >> 4) * 16;
        #pragma unroll
        for (int ks = 0; ks < 4; ks++) ldm4(qa[tb][ks], qbase + ks * 32);
    }

    float o[2][8][4];
    #pragma unroll
    for (int tb = 0; tb < 2; tb++)
        #pragma unroll
        for (int nt = 0; nt < 8; nt++)
            { o[tb][nt][0]=0.f; o[tb][nt][1]=0.f; o[tb][nt][2]=0.f; o[tb][nt][3]=0.f; }
    float m[2][2] = { {-1e30f, -1e30f}, {-1e30f, -1e30f} };
    float l[2][2] = { {0.f, 0.f}, {0.f, 0.f} };

    // per-thread ldmatrix base addrs
    const uint32_t kfb = sb + SM_K16 + (lane & 7) * RSTRIDE + (lane >> 3) * 16;
    const uint32_t vfb = sb + SM_V16 + lane * RSTRIDE;

    for (int j = 0; j < ntiles; j++) {
        asm volatile("cp.async.wait_group 0;" ::: "memory");
        __syncthreads();                         // tile j f32 visible; prev compute done

        // ---- convert f32 -> fp16 (K and V, 144B-stride rows) ----
        {
            const float4* K4 = reinterpret_cast<const float4*>(smem + SM_F32K);
            const float4* V4 = reinterpret_cast<const float4*>(smem + SM_F32V);
            char* k16 = smem + SM_K16;
            char* v16 = smem + SM_V16;
            #pragma unroll
            for (int i = 0; i < 4; i++) {
                int ci = tid + i * 128;
                int dst = (ci >> 3) * RSTRIDE + (ci & 7) * 16;
                float4 x = K4[2 * ci], y = K4[2 * ci + 1];
                uint4 h;
                h.x = pk(x.x, x.y); h.y = pk(x.z, x.w);
                h.z = pk(y.x, y.y); h.w = pk(y.z, y.w);
                *reinterpret_cast<uint4*>(k16 + dst) = h;
                x = V4[2 * ci]; y = V4[2 * ci + 1];
                h.x = pk(x.x, x.y); h.y = pk(x.z, x.w);
                h.z = pk(y.x, y.y); h.w = pk(y.z, y.w);
                *reinterpret_cast<uint4*>(v16 + dst) = h;
            }
        }
        __syncthreads();

        // ---- prefetch tile j+1 (overlaps with compute below) ----
        if (j + 1 < ntiles) {
            const float* Kt = Kb + (size_t)(j + 1) * BC * D_;
            const float* Vt = Vb + (size_t)(j + 1) * BC * D_;
            #pragma unroll
            for (int i = 0; i < 8; i++) {
                int f = tid + i * 128;
                cpa16(sb + SM_F32K + f * 16, Kt + f * 4);
                cpa16(sb + SM_F32V + f * 16, Vt + f * 4);
            }
            asm volatile("cp.async.commit_group;" ::: "memory");
        }

        // ---- S = Q K^T : K frags shared by both row-tiles ----
        float s[2][8][4];
        #pragma unroll
        for (int tb = 0; tb < 2; tb++)
            #pragma unroll
            for (int nt = 0; nt < 8; nt++)
                { s[tb][nt][0]=0.f; s[tb][nt][1]=0.f; s[tb][nt][2]=0.f; s[tb][nt][3]=0.f; }
        #pragma unroll
        for (int nt = 0; nt < 8; nt++) {
            uint32_t b[8];
            ldm4(b,     kfb + nt * (8 * RSTRIDE));          // k chunks 0..3
            ldm4(b + 4, kfb + nt * (8 * RSTRIDE) + 64);     // k chunks 4..7
            #pragma unroll
            for (int ks = 0; ks < 4; ks++) {
                mma16816(s[0][nt], qa[0][ks], b[2*ks], b[2*ks+1]);
                mma16816(s[1][nt], qa[1][ks], b[2*ks], b[2*ks+1]);
            }
        }

        // ---- causal mask (diagonal region spans key tiles 2qt, 2qt+1) ----
        if (msk && j >= 2 * qt) {
            #pragma unroll
            for (int tb = 0; tb < 2; tb++) {
                const int row0 = qt * BR + w * 32 + tb * 16 + g;
                #pragma unroll
                for (int nt = 0; nt < 8; nt++) {
                    int col = j * BC + nt * 8 + 2 * t;
                    if (col     > row0)     s[tb][nt][0] = -1e30f;
                    if (col + 1 > row0)     s[tb][nt][1] = -1e30f;
                    if (col     > row0 + 8) s[tb][nt][2] = -1e30f;
                    if (col + 1 > row0 + 8) s[tb][nt][3] = -1e30f;
                }
            }
        }

        // ---- online softmax (base-2) + P pack, per row-tile ----
        uint32_t pa[2][4][4];
        #pragma unroll
        for (int tb = 0; tb < 2; tb++) {
            float tm0 = -1e30f, tm1 = -1e30f;
            #pragma unroll
            for (int nt = 0; nt < 8; nt++) {
                tm0 = fmaxf(tm0, fmaxf(s[tb][nt][0], s[tb][nt][1]));
                tm1 = fmaxf(tm1, fmaxf(s[tb][nt][2], s[tb][nt][3]));
            }
            #pragma unroll
            for (int off = 1; off < 4; off <<= 1) {
                tm0 = fmaxf(tm0, __shfl_xor_sync(0xffffffffu, tm0, off));
                tm1 = fmaxf(tm1, __shfl_xor_sync(0xffffffffu, tm1, off));
            }
            const float mn0 = fmaxf(m[tb][0], tm0), mn1 = fmaxf(m[tb][1], tm1);
            const float c0 = ex2f(m[tb][0] - mn0), c1 = ex2f(m[tb][1] - mn1);
            float ps0 = 0.f, ps1 = 0.f;
            #pragma unroll
            for (int nt = 0; nt < 8; nt++) {
                s[tb][nt][0] = ex2f(s[tb][nt][0] - mn0);
                s[tb][nt][1] = ex2f(s[tb][nt][1] - mn0);
                s[tb][nt][2] = ex2f(s[tb][nt][2] - mn1);
                s[tb][nt][3] = ex2f(s[tb][nt][3] - mn1);
                ps0 += s[tb][nt][0] + s[tb][nt][1];
                ps1 += s[tb][nt][2] + s[tb][nt][3];
            }
            l[tb][0] = l[tb][0] * c0 + ps0;  l[tb][1] = l[tb][1] * c1 + ps1;
            m[tb][0] = mn0;                  m[tb][1] = mn1;
            #pragma unroll
            for (int nt = 0; nt < 8; nt++) {
                o[tb][nt][0] *= c0; o[tb][nt][1] *= c0;
                o[tb][nt][2] *= c1; o[tb][nt][3] *= c1;
            }
            #pragma unroll
            for (int ks = 0; ks < 4; ks++) {
                pa[tb][ks][0] = pk(s[tb][2*ks][0],   s[tb][2*ks][1]);
                pa[tb][ks][1] = pk(s[tb][2*ks][2],   s[tb][2*ks][3]);
                pa[tb][ks][2] = pk(s[tb][2*ks+1][0], s[tb][2*ks+1][1]);
                pa[tb][ks][3] = pk(s[tb][2*ks+1][2], s[tb][2*ks+1][3]);
            }
        }

        // ---- O += P V : V frags shared by both row-tiles ----
        #pragma unroll
        for (int nt = 0; nt < 8; nt++) {
            uint32_t b[8];
            ldm4t(b,     vfb + nt * 16);                    // s rows 0..31
            ldm4t(b + 4, vfb + nt * 16 + 32 * RSTRIDE);     // s rows 32..63
            #pragma unroll
            for (int ks = 0; ks < 4; ks++) {
                mma16816(o[0][nt], pa[0][ks], b[2*ks], b[2*ks+1]);
                mma16816(o[1][nt], pa[1][ks], b[2*ks], b[2*ks+1]);
            }
        }
    }

    // ---- epilogue ----
    #pragma unroll
    for (int tb = 0; tb < 2; tb++) {
        #pragma unroll
        for (int off = 1; off < 4; off <<= 1) {
            l[tb][0] += __shfl_xor_sync(0xffffffffu, l[tb][0], off);
            l[tb][1] += __shfl_xor_sync(0xffffffffu, l[tb][1], off);
        }
    }
    float* Ob = O + (size_t)bh * S_ * D_;
    #pragma unroll
    for (int tb = 0; tb < 2; tb++) {
        const float inv0 = 1.f / l[tb][0], inv1 = 1.f / l[tb][1];
        const int row0 = qt * BR + w * 32 + tb * 16 + g;
        #pragma unroll
        for (int nt = 0; nt < 8; nt++) {
            int col = nt * 8 + 2 * t;
            *reinterpret_cast<float2*>(Ob + (size_t)row0 * D_ + col) =
                make_float2(o[tb][nt][0] * inv0, o[tb][nt][1] * inv0);
            *reinterpret_cast<float2*>(Ob + (size_t)(row0 + 8) * D_ + col) =
                make_float2(o[tb][nt][2] * inv1, o[tb][nt][3] * inv1);
        }
    }
}

extern "C" void kernel_launch(void* const* d_in, const int* in_sizes, int n_in,
                              void* d_out, int out_size) {
    const float* Q = (const float*)d_in[0];
    const float* K = (const float*)d_in[1];
    const float* V = (const float*)d_in[2];
    const int* msk = (const int*)d_in[3];
    float* O = (float*)d_out;

    cudaFuncSetAttribute(fa_fp16_v2, cudaFuncAttributeMaxDynamicSharedMemorySize, SM_BYTES);
    dim3 grid(S_ / BR, B_ * H_);
    fa_fp16_v2<<<grid, 128, SM_BYTES>>>(Q, K, V, msk, O);
}